// round 1
// baseline (speedup 1.0000x reference)
#include <cuda_runtime.h>

// ---------------- constants ----------------
constexpr int THREADS = 512;
constexpr int WARPS   = THREADS / 32;

// smem layout (floats)
constexpr int SM_W0   = 0;                 // 40 rows x stride 66 (padded)
constexpr int SM_W1   = 40 * 66;           // 2640 : 64 x 128
constexpr int SM_WE   = SM_W1 + 64 * 128;  // 10832 : 128 x 160
constexpr int SM_C    = SM_WE + 128 * 160; // 31312 : bessel[8], tpw[7]
constexpr int SM_BUF  = SM_C + 16;         // 31328 : WARPS * 32 * 33
constexpr int SMEM_FLOATS = SM_BUF + WARPS * 32 * 33;
constexpr int SMEM_BYTES  = SMEM_FLOATS * 4; // 192,896 B

__device__ __forceinline__ float silu_f(float v) {
    return v / (1.0f + __expf(-v));
}

__global__ void __launch_bounds__(THREADS, 1)
e3_fused_kernel(const int*   __restrict__ eidx,
                const float* __restrict__ esh,
                const float* __restrict__ elen,
                const float* __restrict__ onehot,
                const float* __restrict__ bw,
                const float* __restrict__ tpw,
                const float* __restrict__ W0,
                const float* __restrict__ W1,
                const float* __restrict__ We,
                float*       __restrict__ out,
                int E)
{
    extern __shared__ float sm[];

    constexpr float S0 = 0.15811388300841897f;   // 1/sqrt(40)
    constexpr float S1 = 1.6789f * 0.125f;       // SILU_CST/sqrt(64)
    constexpr float S2 = 0.08838834764831845f;   // 1/sqrt(128)

    // ---- cooperative weight load (pre-scaled) ----
    for (int i = threadIdx.x; i < 40 * 64; i += THREADS) {
        int r = i >> 6, k = i & 63;
        sm[SM_W0 + r * 66 + k] = W0[i] * S0;
    }
    for (int i = threadIdx.x; i < 64 * 128; i += THREADS)
        sm[SM_W1 + i] = W1[i] * S1;
    for (int i = threadIdx.x; i < 128 * 160; i += THREADS)
        sm[SM_WE + i] = We[i] * S2;
    if (threadIdx.x < 8)       sm[SM_C + threadIdx.x] = bw[threadIdx.x];
    else if (threadIdx.x < 15) sm[SM_C + threadIdx.x] = tpw[threadIdx.x - 8];
    __syncthreads();

    const int lane  = threadIdx.x & 31;
    const int warp  = threadIdx.x >> 5;
    float* buf      = sm + SM_BUF + warp * (32 * 33);
    const int e     = blockIdx.x * THREADS + threadIdx.x;
    const int ebase = blockIdx.x * THREADS + warp * 32;

    float* __restrict__ lat_out  = out;
    float* __restrict__ feat_out = out + (size_t)E * 128;
    float* __restrict__ cut_out  = out + (size_t)E * 416;

    // ---- per-edge loads ----
    const int   src = eidx[e];
    const int   dst = eidx[E + e];
    const float r   = elen[e];
    const float4 shv = reinterpret_cast<const float4*>(esh)[e];

    // decode one-hot types (exact 0/1 by construction)
    int ts = 0, td = 0;
    {
        const float4* rs = reinterpret_cast<const float4*>(onehot + (size_t)src * 16);
        const float4* rd = reinterpret_cast<const float4*>(onehot + (size_t)dst * 16);
#pragma unroll
        for (int q4 = 0; q4 < 4; q4++) {
            float4 a = rs[q4];
            float4 b = rd[q4];
            int base = q4 * 4;
            if (a.x > 0.5f) ts = base;     if (a.y > 0.5f) ts = base + 1;
            if (a.z > 0.5f) ts = base + 2; if (a.w > 0.5f) ts = base + 3;
            if (b.x > 0.5f) td = base;     if (b.y > 0.5f) td = base + 1;
            if (b.z > 0.5f) td = base + 2; if (b.w > 0.5f) td = base + 3;
        }
    }

    // ---- bessel + cutoff ----
    const float x    = r * 0.2f;       // r / R_MAX
    const float invr = 1.0f / r;
    float eb[8];
#pragma unroll
    for (int j = 0; j < 8; j++)
        eb[j] = 0.4f * __sinf(sm[SM_C + j] * x) * invr;  // 2/R_MAX * sin(w*x)/r

    const float x2 = x * x, x3 = x2 * x, x6 = x3 * x3, x7 = x6 * x, x8 = x7 * x;
    const float poly = 1.0f - 28.0f * x6 + 48.0f * x7 - 21.0f * x8;
    const float cutv = (x < 1.0f) ? poly : 0.0f;
    const float cl   = (cutv > 0.0f) ? cutv : 0.0f;   // mask * cut
    cut_out[e] = cutv;

    // ---- stage 1: h[64] = silu( onehot-gather + eb @ W0 ) ----
    float hloc[64];  // local mem (dynamically indexed below)
    {
        float acc[64];
        const float* w0s = sm + SM_W0 + ts * 66;
        const float* w0d = sm + SM_W0 + (16 + td) * 66;
#pragma unroll
        for (int k = 0; k < 64; k++) acc[k] = w0s[k] + w0d[k];
#pragma unroll
        for (int j = 0; j < 8; j++) {
            const float b = eb[j];
            const float* wr = sm + SM_W0 + (32 + j) * 66;
#pragma unroll
            for (int k = 0; k < 64; k++) acc[k] = fmaf(b, wr[k], acc[k]);
        }
#pragma unroll
        for (int k = 0; k < 64; k++) hloc[k] = silu_f(acc[k]);
    }

    // ---- stage 2: lat[128] = cl * (h @ W1); coalesced latents out ----
    float latloc[128];  // local mem
#pragma unroll
    for (int p = 0; p < 2; p++) {
        float acc[64];
#pragma unroll
        for (int k = 0; k < 64; k++) acc[k] = 0.0f;
        const float* wp = sm + SM_W1 + p * 64;
#pragma unroll 4
        for (int j = 0; j < 64; j++) {
            const float hj = hloc[j];
            const float* wr = wp + j * 128;
#pragma unroll
            for (int k = 0; k < 64; k++) acc[k] = fmaf(hj, wr[k], acc[k]);
        }
#pragma unroll
        for (int k = 0; k < 64; k++) { acc[k] *= cl; latloc[p * 64 + k] = acc[k]; }
        // transpose-stage two 32-col windows -> coalesced STG
#pragma unroll
        for (int wdw = 0; wdw < 2; wdw++) {
#pragma unroll
            for (int u = 0; u < 32; u++) buf[lane * 33 + u] = acc[wdw * 32 + u];
            __syncwarp();
#pragma unroll
            for (int rr = 0; rr < 32; rr++)
                lat_out[(size_t)(ebase + rr) * 128 + p * 64 + wdw * 32 + lane] =
                    buf[rr * 33 + lane];
            __syncwarp();
        }
    }

    // ---- tensor-product scalars ----
    const float s = shv.x, vx = shv.y, vy = shv.z, vz = shv.w;
    const float tw0 = sm[SM_C +  8], tw1 = sm[SM_C +  9], tw2 = sm[SM_C + 10];
    const float tw3 = sm[SM_C + 11], tw4 = sm[SM_C + 12], tw5 = sm[SM_C + 13];
    const float tw6 = sm[SM_C + 14];
    constexpr float SQ3  = 1.7320508075688772f;
    constexpr float INV2 = 0.70710678118654752f;

    const float sq   = s * s;
    const float dotv = (vx * vx + vy * vy + vz * vz) * (1.0f / SQ3);
    const float tp0a = tw0 * sq + tw1 * dotv;
    const float tp0b = tw4 * sq + tw5 * dotv;
    float tp1a[3], tp1b[3];
    tp1a[0] = tw2 * s * vx; tp1a[1] = tw2 * s * vy; tp1a[2] = tw2 * s * vz;
    tp1b[0] = tw3 * s * vx; tp1b[1] = tw3 * s * vy; tp1b[2] = tw3 * s * vz;
    float tp2[5];
    tp2[0] = tw6 * SQ3 * vx * vy;
    tp2[1] = tw6 * SQ3 * vy * vz;
    tp2[2] = tw6 * (vz * vz - 0.5f * (vx * vx + vy * vy));
    tp2[3] = tw6 * SQ3 * vx * vz;
    tp2[4] = tw6 * (0.5f * SQ3) * (vx * vx - vy * vy);

    // ---- stage 3 pass A: w cols 0..63 (w0a | w0b) -> f0 ----
    {
        float acc[64];
#pragma unroll
        for (int k = 0; k < 64; k++) acc[k] = 0.0f;
#pragma unroll 4
        for (int j = 0; j < 128; j++) {
            const float lj = latloc[j];
            const float* wr = sm + SM_WE + j * 160;
#pragma unroll
            for (int k = 0; k < 64; k++) acc[k] = fmaf(lj, wr[k], acc[k]);
        }
#pragma unroll
        for (int u = 0; u < 32; u++)
            buf[lane * 33 + u] = INV2 * (acc[u] * tp0a + acc[32 + u] * tp0b);
        __syncwarp();
#pragma unroll
        for (int rr = 0; rr < 32; rr++)
            feat_out[(size_t)(ebase + rr) * 288 + 0 + lane] = buf[rr * 33 + lane];
        __syncwarp();
    }

    // ---- stage 3 pass B: w cols 64..127 (w1a | w1b) -> f1 (96 cols) ----
    {
        float acc[64];
#pragma unroll
        for (int k = 0; k < 64; k++) acc[k] = 0.0f;
#pragma unroll 4
        for (int j = 0; j < 128; j++) {
            const float lj = latloc[j];
            const float* wr = sm + SM_WE + j * 160 + 64;
#pragma unroll
            for (int k = 0; k < 64; k++) acc[k] = fmaf(lj, wr[k], acc[k]);
        }
#pragma unroll
        for (int t = 0; t < 3; t++) {
#pragma unroll
            for (int u = 0; u < 32; u++) {
                const int cc = 32 * t + u, m = cc / 3, i = cc % 3;
                buf[lane * 33 + u] = INV2 * (acc[m] * tp1a[i] + acc[32 + m] * tp1b[i]);
            }
            __syncwarp();
#pragma unroll
            for (int rr = 0; rr < 32; rr++)
                feat_out[(size_t)(ebase + rr) * 288 + 32 + 32 * t + lane] =
                    buf[rr * 33 + lane];
            __syncwarp();
        }
    }

    // ---- stage 3 pass C: w cols 128..159 (w2) -> f2 (160 cols) ----
    {
        float acc[32];
#pragma unroll
        for (int k = 0; k < 32; k++) acc[k] = 0.0f;
#pragma unroll 4
        for (int j = 0; j < 128; j++) {
            const float lj = latloc[j];
            const float* wr = sm + SM_WE + j * 160 + 128;
#pragma unroll
            for (int k = 0; k < 32; k++) acc[k] = fmaf(lj, wr[k], acc[k]);
        }
#pragma unroll
        for (int t = 0; t < 5; t++) {
#pragma unroll
            for (int u = 0; u < 32; u++) {
                const int cc = 32 * t + u, m = cc / 5, i = cc % 5;
                buf[lane * 33 + u] = acc[m] * tp2[i];
            }
            __syncwarp();
#pragma unroll
            for (int rr = 0; rr < 32; rr++)
                feat_out[(size_t)(ebase + rr) * 288 + 128 + 32 * t + lane] =
                    buf[rr * 33 + lane];
            __syncwarp();
        }
    }
}

extern "C" void kernel_launch(void* const* d_in, const int* in_sizes, int n_in,
                              void* d_out, int out_size)
{
    const int*   eidx   = (const int*)  d_in[0];
    const float* esh    = (const float*)d_in[1];
    const float* elen   = (const float*)d_in[2];
    const float* onehot = (const float*)d_in[3];
    const float* bw     = (const float*)d_in[4];
    const float* tpw    = (const float*)d_in[5];
    const float* W0     = (const float*)d_in[6];
    const float* W1     = (const float*)d_in[7];
    const float* We     = (const float*)d_in[8];
    float* out = (float*)d_out;

    const int E = in_sizes[0] / 2;       // edge_index is (2, E)
    const int blocks = E / THREADS;      // E = 524288 -> 1024 blocks

    cudaFuncSetAttribute(e3_fused_kernel,
                         cudaFuncAttributeMaxDynamicSharedMemorySize, SMEM_BYTES);
    e3_fused_kernel<<<blocks, THREADS, SMEM_BYTES>>>(
        eidx, esh, elen, onehot, bw, tpw, W0, W1, We, out, E);
}

// round 2
// speedup vs baseline: 1.0398x; 1.0398x over previous
#include <cuda_runtime.h>

typedef unsigned long long u64;

// ---------------- constants ----------------
constexpr int THREADS = 512;
constexpr int WARPS   = THREADS / 32;

// smem layout (floats)
constexpr int SM_W0   = 0;                  // 40 rows x stride 68 (16B-aligned rows)
constexpr int SM_W1   = 40 * 68;            // 2720 : 64 x 128
constexpr int SM_WE   = SM_W1 + 64 * 128;   // 10912 : 128 x 160
constexpr int SM_C    = SM_WE + 128 * 160;  // 31392 : bessel[8], tpw[7]
constexpr int SM_BUF  = SM_C + 16;          // 31408 : WARPS * 32 * 33
constexpr int SMEM_FLOATS = SM_BUF + WARPS * 32 * 33;
constexpr int SMEM_BYTES  = SMEM_FLOATS * 4; // 193,216 B

// ---------------- f32x2 packed helpers ----------------
__device__ __forceinline__ u64 pk2(float lo, float hi) {
    u64 r; asm("mov.b64 %0, {%1, %2};" : "=l"(r) : "f"(lo), "f"(hi)); return r;
}
__device__ __forceinline__ void up2(float& lo, float& hi, u64 a) {
    asm("mov.b64 {%0, %1}, %2;" : "=f"(lo), "=f"(hi) : "l"(a));
}
__device__ __forceinline__ u64 fma2(u64 a, u64 b, u64 c) {
    u64 d; asm("fma.rn.f32x2 %0, %1, %2, %3;" : "=l"(d) : "l"(a), "l"(b), "l"(c)); return d;
}
__device__ __forceinline__ u64 add2(u64 a, u64 b) {
    u64 d; asm("add.rn.f32x2 %0, %1, %2;" : "=l"(d) : "l"(a), "l"(b)); return d;
}
__device__ __forceinline__ u64 mul2(u64 a, u64 b) {
    u64 d; asm("mul.rn.f32x2 %0, %1, %2;" : "=l"(d) : "l"(a), "l"(b)); return d;
}

__device__ __forceinline__ float silu_f(float v) {
    return v / (1.0f + __expf(-v));
}

__global__ void __launch_bounds__(THREADS, 1)
e3_fused_kernel(const int*   __restrict__ eidx,
                const float* __restrict__ esh,
                const float* __restrict__ elen,
                const float* __restrict__ onehot,
                const float* __restrict__ bw,
                const float* __restrict__ tpw,
                const float* __restrict__ W0,
                const float* __restrict__ W1,
                const float* __restrict__ We,
                float*       __restrict__ out,
                int E)
{
    extern __shared__ float sm[];

    constexpr float S0 = 0.15811388300841897f;   // 1/sqrt(40)
    constexpr float S1 = 1.6789f * 0.125f;       // SILU_CST/sqrt(64)
    constexpr float S2 = 0.08838834764831845f;   // 1/sqrt(128)

    // ---- cooperative weight load (pre-scaled) ----
    for (int i = threadIdx.x; i < 40 * 64; i += THREADS) {
        int r = i >> 6, k = i & 63;
        sm[SM_W0 + r * 68 + k] = W0[i] * S0;
    }
    for (int i = threadIdx.x; i < 64 * 128; i += THREADS)
        sm[SM_W1 + i] = W1[i] * S1;
    for (int i = threadIdx.x; i < 128 * 160; i += THREADS)
        sm[SM_WE + i] = We[i] * S2;
    if (threadIdx.x < 8)       sm[SM_C + threadIdx.x] = bw[threadIdx.x];
    else if (threadIdx.x < 15) sm[SM_C + threadIdx.x] = tpw[threadIdx.x - 8];
    __syncthreads();

    const int lane  = threadIdx.x & 31;
    const int warp  = threadIdx.x >> 5;
    float* buf      = sm + SM_BUF + warp * (32 * 33);
    const int e     = blockIdx.x * THREADS + threadIdx.x;
    const int ebase = blockIdx.x * THREADS + warp * 32;

    float* __restrict__ lat_out  = out;
    float* __restrict__ feat_out = out + (size_t)E * 128;
    float* __restrict__ cut_out  = out + (size_t)E * 416;

    // ---- per-edge loads ----
    const int   src = eidx[e];
    const int   dst = eidx[E + e];
    const float r   = elen[e];
    const float4 shv = reinterpret_cast<const float4*>(esh)[e];

    // decode one-hot types (exact 0/1 by construction)
    int ts = 0, td = 0;
    {
        const float4* rs = reinterpret_cast<const float4*>(onehot + (size_t)src * 16);
        const float4* rd = reinterpret_cast<const float4*>(onehot + (size_t)dst * 16);
#pragma unroll
        for (int q4 = 0; q4 < 4; q4++) {
            float4 a = rs[q4];
            float4 b = rd[q4];
            int base = q4 * 4;
            if (a.x > 0.5f) ts = base;     if (a.y > 0.5f) ts = base + 1;
            if (a.z > 0.5f) ts = base + 2; if (a.w > 0.5f) ts = base + 3;
            if (b.x > 0.5f) td = base;     if (b.y > 0.5f) td = base + 1;
            if (b.z > 0.5f) td = base + 2; if (b.w > 0.5f) td = base + 3;
        }
    }

    // ---- bessel + cutoff ----
    const float x    = r * 0.2f;       // r / R_MAX
    const float invr = 1.0f / r;
    float eb[8];
#pragma unroll
    for (int j = 0; j < 8; j++)
        eb[j] = 0.4f * __sinf(sm[SM_C + j] * x) * invr;  // 2/R_MAX * sin(w*x)/r

    const float x2 = x * x, x3 = x2 * x, x6 = x3 * x3, x7 = x6 * x, x8 = x7 * x;
    const float poly = 1.0f - 28.0f * x6 + 48.0f * x7 - 21.0f * x8;
    const float cutv = (x < 1.0f) ? poly : 0.0f;
    const float cl   = (cutv > 0.0f) ? cutv : 0.0f;   // mask * cut
    cut_out[e] = cutv;

    // ---- stage 1: h[64] = silu( onehot-gather + eb @ W0 ) ----
    float hloc[64];  // local mem
    {
        u64 acc[32];
        const ulonglong2* w0s = reinterpret_cast<const ulonglong2*>(sm + SM_W0 + ts * 68);
        const ulonglong2* w0d = reinterpret_cast<const ulonglong2*>(sm + SM_W0 + (16 + td) * 68);
#pragma unroll
        for (int q = 0; q < 16; q++) {
            ulonglong2 a = w0s[q];
            ulonglong2 b = w0d[q];
            acc[2 * q]     = add2(a.x, b.x);
            acc[2 * q + 1] = add2(a.y, b.y);
        }
#pragma unroll
        for (int j = 0; j < 8; j++) {
            const u64 b2 = pk2(eb[j], eb[j]);
            const ulonglong2* wr = reinterpret_cast<const ulonglong2*>(sm + SM_W0 + (32 + j) * 68);
#pragma unroll
            for (int q = 0; q < 16; q++) {
                ulonglong2 w = wr[q];
                acc[2 * q]     = fma2(b2, w.x, acc[2 * q]);
                acc[2 * q + 1] = fma2(b2, w.y, acc[2 * q + 1]);
            }
        }
#pragma unroll
        for (int q = 0; q < 32; q++) {
            float a, b; up2(a, b, acc[q]);
            hloc[2 * q]     = silu_f(a);
            hloc[2 * q + 1] = silu_f(b);
        }
    }

    // ---- stage 2: lat[128] = cl * (h @ W1); coalesced latents out ----
    float latloc[128];  // local mem
    const u64 cl2 = pk2(cl, cl);
#pragma unroll
    for (int p = 0; p < 2; p++) {
        u64 acc[32];
#pragma unroll
        for (int q = 0; q < 32; q++) acc[q] = 0ull;
        const float* wp = sm + SM_W1 + p * 64;
#pragma unroll 4
        for (int j = 0; j < 64; j++) {
            const float hj = hloc[j];
            const u64 h2 = pk2(hj, hj);
            const ulonglong2* wr = reinterpret_cast<const ulonglong2*>(wp + j * 128);
#pragma unroll
            for (int q = 0; q < 16; q++) {
                ulonglong2 w = wr[q];
                acc[2 * q]     = fma2(h2, w.x, acc[2 * q]);
                acc[2 * q + 1] = fma2(h2, w.y, acc[2 * q + 1]);
            }
        }
#pragma unroll
        for (int q = 0; q < 32; q++) {
            acc[q] = mul2(cl2, acc[q]);
            float a, b; up2(a, b, acc[q]);
            latloc[p * 64 + 2 * q]     = a;
            latloc[p * 64 + 2 * q + 1] = b;
        }
        // transpose-stage two 32-col windows -> coalesced STG
#pragma unroll
        for (int wdw = 0; wdw < 2; wdw++) {
#pragma unroll
            for (int u = 0; u < 32; u++)
                buf[lane * 33 + u] = latloc[p * 64 + wdw * 32 + u];
            __syncwarp();
#pragma unroll
            for (int rr = 0; rr < 32; rr++)
                lat_out[(size_t)(ebase + rr) * 128 + p * 64 + wdw * 32 + lane] =
                    buf[rr * 33 + lane];
            __syncwarp();
        }
    }

    // ---- tensor-product scalars ----
    const float s = shv.x, vx = shv.y, vy = shv.z, vz = shv.w;
    const float tw0 = sm[SM_C +  8], tw1 = sm[SM_C +  9], tw2 = sm[SM_C + 10];
    const float tw3 = sm[SM_C + 11], tw4 = sm[SM_C + 12], tw5 = sm[SM_C + 13];
    const float tw6 = sm[SM_C + 14];
    constexpr float SQ3  = 1.7320508075688772f;
    constexpr float INV2 = 0.70710678118654752f;

    const float sq   = s * s;
    const float dotv = (vx * vx + vy * vy + vz * vz) * (1.0f / SQ3);
    const float tp0a = tw0 * sq + tw1 * dotv;
    const float tp0b = tw4 * sq + tw5 * dotv;
    float tp1a[3], tp1b[3];
    tp1a[0] = tw2 * s * vx; tp1a[1] = tw2 * s * vy; tp1a[2] = tw2 * s * vz;
    tp1b[0] = tw3 * s * vx; tp1b[1] = tw3 * s * vy; tp1b[2] = tw3 * s * vz;
    float tp2[5];
    tp2[0] = tw6 * SQ3 * vx * vy;
    tp2[1] = tw6 * SQ3 * vy * vz;
    tp2[2] = tw6 * (vz * vz - 0.5f * (vx * vx + vy * vy));
    tp2[3] = tw6 * SQ3 * vx * vz;
    tp2[4] = tw6 * (0.5f * SQ3) * (vx * vx - vy * vy);

    // ---- stage 3 pass A: w cols 0..63 (w0a | w0b) -> f0 ----
    {
        u64 acc[32];
#pragma unroll
        for (int q = 0; q < 32; q++) acc[q] = 0ull;
#pragma unroll 4
        for (int j = 0; j < 128; j++) {
            const float lj = latloc[j];
            const u64 l2 = pk2(lj, lj);
            const ulonglong2* wr = reinterpret_cast<const ulonglong2*>(sm + SM_WE + j * 160);
#pragma unroll
            for (int q = 0; q < 16; q++) {
                ulonglong2 w = wr[q];
                acc[2 * q]     = fma2(l2, w.x, acc[2 * q]);
                acc[2 * q + 1] = fma2(l2, w.y, acc[2 * q + 1]);
            }
        }
        float accf[64];
#pragma unroll
        for (int q = 0; q < 32; q++) up2(accf[2 * q], accf[2 * q + 1], acc[q]);
#pragma unroll
        for (int u = 0; u < 32; u++)
            buf[lane * 33 + u] = INV2 * (accf[u] * tp0a + accf[32 + u] * tp0b);
        __syncwarp();
#pragma unroll
        for (int rr = 0; rr < 32; rr++)
            feat_out[(size_t)(ebase + rr) * 288 + 0 + lane] = buf[rr * 33 + lane];
        __syncwarp();
    }

    // ---- stage 3 pass B: w cols 64..127 (w1a | w1b) -> f1 (96 cols) ----
    {
        u64 acc[32];
#pragma unroll
        for (int q = 0; q < 32; q++) acc[q] = 0ull;
#pragma unroll 4
        for (int j = 0; j < 128; j++) {
            const float lj = latloc[j];
            const u64 l2 = pk2(lj, lj);
            const ulonglong2* wr = reinterpret_cast<const ulonglong2*>(sm + SM_WE + j * 160 + 64);
#pragma unroll
            for (int q = 0; q < 16; q++) {
                ulonglong2 w = wr[q];
                acc[2 * q]     = fma2(l2, w.x, acc[2 * q]);
                acc[2 * q + 1] = fma2(l2, w.y, acc[2 * q + 1]);
            }
        }
        float accf[64];
#pragma unroll
        for (int q = 0; q < 32; q++) up2(accf[2 * q], accf[2 * q + 1], acc[q]);
#pragma unroll
        for (int t = 0; t < 3; t++) {
#pragma unroll
            for (int u = 0; u < 32; u++) {
                const int cc = 32 * t + u, m = cc / 3, i = cc % 3;
                buf[lane * 33 + u] = INV2 * (accf[m] * tp1a[i] + accf[32 + m] * tp1b[i]);
            }
            __syncwarp();
#pragma unroll
            for (int rr = 0; rr < 32; rr++)
                feat_out[(size_t)(ebase + rr) * 288 + 32 + 32 * t + lane] =
                    buf[rr * 33 + lane];
            __syncwarp();
        }
    }

    // ---- stage 3 pass C: w cols 128..159 (w2) -> f2 (160 cols) ----
    {
        u64 acc[16];
#pragma unroll
        for (int q = 0; q < 16; q++) acc[q] = 0ull;
#pragma unroll 4
        for (int j = 0; j < 128; j++) {
            const float lj = latloc[j];
            const u64 l2 = pk2(lj, lj);
            const ulonglong2* wr = reinterpret_cast<const ulonglong2*>(sm + SM_WE + j * 160 + 128);
#pragma unroll
            for (int q = 0; q < 8; q++) {
                ulonglong2 w = wr[q];
                acc[2 * q]     = fma2(l2, w.x, acc[2 * q]);
                acc[2 * q + 1] = fma2(l2, w.y, acc[2 * q + 1]);
            }
        }
        float accf[32];
#pragma unroll
        for (int q = 0; q < 16; q++) up2(accf[2 * q], accf[2 * q + 1], acc[q]);
#pragma unroll
        for (int t = 0; t < 5; t++) {
#pragma unroll
            for (int u = 0; u < 32; u++) {
                const int cc = 32 * t + u, m = cc / 5, i = cc % 5;
                buf[lane * 33 + u] = accf[m] * tp2[i];
            }
            __syncwarp();
#pragma unroll
            for (int rr = 0; rr < 32; rr++)
                feat_out[(size_t)(ebase + rr) * 288 + 128 + 32 * t + lane] =
                    buf[rr * 33 + lane];
            __syncwarp();
        }
    }
}

extern "C" void kernel_launch(void* const* d_in, const int* in_sizes, int n_in,
                              void* d_out, int out_size)
{
    const int*   eidx   = (const int*)  d_in[0];
    const float* esh    = (const float*)d_in[1];
    const float* elen   = (const float*)d_in[2];
    const float* onehot = (const float*)d_in[3];
    const float* bw     = (const float*)d_in[4];
    const float* tpw    = (const float*)d_in[5];
    const float* W0     = (const float*)d_in[6];
    const float* W1     = (const float*)d_in[7];
    const float* We     = (const float*)d_in[8];
    float* out = (float*)d_out;

    const int E = in_sizes[0] / 2;       // edge_index is (2, E)
    const int blocks = E / THREADS;      // E = 524288 -> 1024 blocks

    cudaFuncSetAttribute(e3_fused_kernel,
                         cudaFuncAttributeMaxDynamicSharedMemorySize, SMEM_BYTES);
    e3_fused_kernel<<<blocks, THREADS, SMEM_BYTES>>>(
        eidx, esh, elen, onehot, bw, tpw, W0, W1, We, out, E);
}

// round 3
// speedup vs baseline: 1.4308x; 1.3760x over previous
#include <cuda_runtime.h>

typedef unsigned long long u64;

// ---------------- constants ----------------
constexpr int THREADS = 512;
constexpr int WARPS   = THREADS / 32;

// smem layout (floats)
constexpr int SM_W0   = 0;                  // 40 rows x stride 68 (16B-aligned rows)
constexpr int SM_W1   = 40 * 68;            // 2720 : 64 x 128
constexpr int SM_WC   = SM_W1 + 64 * 128;   // 10912 : 64 x 160 (W1 @ W_env, prescaled)
constexpr int SM_C    = SM_WC + 64 * 160;   // 21152 : bessel[8], tpw[7]
constexpr int SM_BUF  = SM_C + 16;          // 21168 : WARPS * 32 * 33
constexpr int SMEM_FLOATS = SM_BUF + WARPS * 32 * 33;
constexpr int SMEM_BYTES  = SMEM_FLOATS * 4; // 152,256 B

// ---------------- device scratch for fused W1@W_env ----------------
__device__ float g_wcombo[64 * 160];

// ---------------- f32x2 packed helpers ----------------
__device__ __forceinline__ u64 pk2(float lo, float hi) {
    u64 r; asm("mov.b64 %0, {%1, %2};" : "=l"(r) : "f"(lo), "f"(hi)); return r;
}
__device__ __forceinline__ void up2(float& lo, float& hi, u64 a) {
    asm("mov.b64 {%0, %1}, %2;" : "=f"(lo), "=f"(hi) : "l"(a));
}
__device__ __forceinline__ u64 fma2(u64 a, u64 b, u64 c) {
    u64 d; asm("fma.rn.f32x2 %0, %1, %2, %3;" : "=l"(d) : "l"(a), "l"(b), "l"(c)); return d;
}
__device__ __forceinline__ u64 add2(u64 a, u64 b) {
    u64 d; asm("add.rn.f32x2 %0, %1, %2;" : "=l"(d) : "l"(a), "l"(b)); return d;
}
__device__ __forceinline__ u64 mul2(u64 a, u64 b) {
    u64 d; asm("mul.rn.f32x2 %0, %1, %2;" : "=l"(d) : "l"(a), "l"(b)); return d;
}

__device__ __forceinline__ float silu_f(float v) {
    return v / (1.0f + __expf(-v));
}

// ---------------- precompute W_combo = (W1*S1) @ (We*S2) ----------------
__global__ void combo_kernel(const float* __restrict__ W1,
                             const float* __restrict__ We)
{
    constexpr float S1 = 1.6789f * 0.125f;       // SILU_CST/sqrt(64)
    constexpr float S2 = 0.08838834764831845f;   // 1/sqrt(128)
    int idx = blockIdx.x * blockDim.x + threadIdx.x;
    if (idx >= 64 * 160) return;
    int r = idx / 160, c = idx % 160;
    float acc = 0.0f;
#pragma unroll 8
    for (int k = 0; k < 128; k++)
        acc = fmaf(W1[r * 128 + k], We[k * 160 + c], acc);
    g_wcombo[idx] = acc * (S1 * S2);
}

__global__ void __launch_bounds__(THREADS, 1)
e3_fused_kernel(const int*   __restrict__ eidx,
                const float* __restrict__ esh,
                const float* __restrict__ elen,
                const float* __restrict__ onehot,
                const float* __restrict__ bw,
                const float* __restrict__ tpw,
                const float* __restrict__ W0,
                const float* __restrict__ W1,
                float*       __restrict__ out,
                int E)
{
    extern __shared__ float sm[];

    constexpr float S0 = 0.15811388300841897f;   // 1/sqrt(40)
    constexpr float S1 = 1.6789f * 0.125f;       // SILU_CST/sqrt(64)

    // ---- cooperative weight load (pre-scaled) ----
    for (int i = threadIdx.x; i < 40 * 64; i += THREADS) {
        int r = i >> 6, k = i & 63;
        sm[SM_W0 + r * 68 + k] = W0[i] * S0;
    }
    for (int i = threadIdx.x; i < 64 * 128; i += THREADS)
        sm[SM_W1 + i] = W1[i] * S1;
    for (int i = threadIdx.x; i < 64 * 160; i += THREADS)
        sm[SM_WC + i] = g_wcombo[i];
    if (threadIdx.x < 8)       sm[SM_C + threadIdx.x] = bw[threadIdx.x];
    else if (threadIdx.x < 15) sm[SM_C + threadIdx.x] = tpw[threadIdx.x - 8];
    __syncthreads();

    const int lane  = threadIdx.x & 31;
    const int warp  = threadIdx.x >> 5;
    float* buf      = sm + SM_BUF + warp * (32 * 33);
    const int e     = blockIdx.x * THREADS + threadIdx.x;
    const int ebase = blockIdx.x * THREADS + warp * 32;

    float* __restrict__ lat_out  = out;
    float* __restrict__ feat_out = out + (size_t)E * 128;
    float* __restrict__ cut_out  = out + (size_t)E * 416;

    // ---- per-edge loads ----
    const int   src = eidx[e];
    const int   dst = eidx[E + e];
    const float r   = elen[e];
    const float4 shv = reinterpret_cast<const float4*>(esh)[e];

    // decode one-hot types (exact 0/1 by construction)
    int ts = 0, td = 0;
    {
        const float4* rs = reinterpret_cast<const float4*>(onehot + (size_t)src * 16);
        const float4* rd = reinterpret_cast<const float4*>(onehot + (size_t)dst * 16);
#pragma unroll
        for (int q4 = 0; q4 < 4; q4++) {
            float4 a = rs[q4];
            float4 b = rd[q4];
            int base = q4 * 4;
            if (a.x > 0.5f) ts = base;     if (a.y > 0.5f) ts = base + 1;
            if (a.z > 0.5f) ts = base + 2; if (a.w > 0.5f) ts = base + 3;
            if (b.x > 0.5f) td = base;     if (b.y > 0.5f) td = base + 1;
            if (b.z > 0.5f) td = base + 2; if (b.w > 0.5f) td = base + 3;
        }
    }

    // ---- bessel + cutoff ----
    const float x    = r * 0.2f;       // r / R_MAX
    const float invr = 1.0f / r;
    float eb[8];
#pragma unroll
    for (int j = 0; j < 8; j++)
        eb[j] = 0.4f * __sinf(sm[SM_C + j] * x) * invr;  // 2/R_MAX * sin(w*x)/r

    const float x2 = x * x, x3 = x2 * x, x6 = x3 * x3, x7 = x6 * x, x8 = x7 * x;
    const float poly = 1.0f - 28.0f * x6 + 48.0f * x7 - 21.0f * x8;
    const float cutv = (x < 1.0f) ? poly : 0.0f;
    const float cl   = (cutv > 0.0f) ? cutv : 0.0f;   // mask * cut
    cut_out[e] = cutv;

    // ---- stage 1: h[64] = silu( onehot-gather + eb @ W0 ) ----
    float hloc[64];  // local mem (dynamically indexed below)
    {
        u64 acc[32];
        const ulonglong2* w0s = reinterpret_cast<const ulonglong2*>(sm + SM_W0 + ts * 68);
        const ulonglong2* w0d = reinterpret_cast<const ulonglong2*>(sm + SM_W0 + (16 + td) * 68);
#pragma unroll
        for (int q = 0; q < 16; q++) {
            ulonglong2 a = w0s[q];
            ulonglong2 b = w0d[q];
            acc[2 * q]     = add2(a.x, b.x);
            acc[2 * q + 1] = add2(a.y, b.y);
        }
#pragma unroll
        for (int j = 0; j < 8; j++) {
            const u64 b2 = pk2(eb[j], eb[j]);
            const ulonglong2* wr = reinterpret_cast<const ulonglong2*>(sm + SM_W0 + (32 + j) * 68);
#pragma unroll
            for (int q = 0; q < 16; q++) {
                ulonglong2 w = wr[q];
                acc[2 * q]     = fma2(b2, w.x, acc[2 * q]);
                acc[2 * q + 1] = fma2(b2, w.y, acc[2 * q + 1]);
            }
        }
#pragma unroll
        for (int q = 0; q < 32; q++) {
            float a, b; up2(a, b, acc[q]);
            hloc[2 * q]     = silu_f(a);
            hloc[2 * q + 1] = silu_f(b);
        }
    }

    // ---- stage 2: lat[128] = cl * (h @ W1) ; coalesced latents out ----
    const u64 cl2 = pk2(cl, cl);
#pragma unroll
    for (int p = 0; p < 2; p++) {
        u64 acc[32];
#pragma unroll
        for (int q = 0; q < 32; q++) acc[q] = 0ull;
        const float* wp = sm + SM_W1 + p * 64;
#pragma unroll 4
        for (int j = 0; j < 64; j++) {
            const float hj = hloc[j];
            const u64 h2 = pk2(hj, hj);
            const ulonglong2* wr = reinterpret_cast<const ulonglong2*>(wp + j * 128);
#pragma unroll
            for (int q = 0; q < 16; q++) {
                ulonglong2 w = wr[q];
                acc[2 * q]     = fma2(h2, w.x, acc[2 * q]);
                acc[2 * q + 1] = fma2(h2, w.y, acc[2 * q + 1]);
            }
        }
        float accf[64];
#pragma unroll
        for (int q = 0; q < 32; q++) {
            acc[q] = mul2(cl2, acc[q]);
            up2(accf[2 * q], accf[2 * q + 1], acc[q]);
        }
        // transpose-stage two 32-col windows -> coalesced STG
#pragma unroll
        for (int wdw = 0; wdw < 2; wdw++) {
#pragma unroll
            for (int u = 0; u < 32; u++)
                buf[lane * 33 + u] = accf[wdw * 32 + u];
            __syncwarp();
#pragma unroll
            for (int rr = 0; rr < 32; rr++)
                lat_out[(size_t)(ebase + rr) * 128 + p * 64 + wdw * 32 + lane] =
                    buf[rr * 33 + lane];
            __syncwarp();
        }
    }

    // ---- tensor-product scalars (cut factor folded in) ----
    const float s = shv.x, vx = shv.y, vy = shv.z, vz = shv.w;
    const float tw0 = sm[SM_C +  8], tw1 = sm[SM_C +  9], tw2 = sm[SM_C + 10];
    const float tw3 = sm[SM_C + 11], tw4 = sm[SM_C + 12], tw5 = sm[SM_C + 13];
    const float tw6 = sm[SM_C + 14];
    constexpr float SQ3  = 1.7320508075688772f;
    constexpr float INV2 = 0.70710678118654752f;

    const float sq   = s * s;
    const float dotv = (vx * vx + vy * vy + vz * vz) * (1.0f / SQ3);
    const float tp0a = (tw0 * sq + tw1 * dotv) * cl;
    const float tp0b = (tw4 * sq + tw5 * dotv) * cl;
    const float scl  = s * cl;
    float tp1a[3], tp1b[3];
    tp1a[0] = tw2 * scl * vx; tp1a[1] = tw2 * scl * vy; tp1a[2] = tw2 * scl * vz;
    tp1b[0] = tw3 * scl * vx; tp1b[1] = tw3 * scl * vy; tp1b[2] = tw3 * scl * vz;
    const float t6c = tw6 * cl;
    float tp2[5];
    tp2[0] = t6c * SQ3 * vx * vy;
    tp2[1] = t6c * SQ3 * vy * vz;
    tp2[2] = t6c * (vz * vz - 0.5f * (vx * vx + vy * vy));
    tp2[3] = t6c * SQ3 * vx * vz;
    tp2[4] = t6c * (0.5f * SQ3) * (vx * vx - vy * vy);

    // ---- stage 3 (fused): wpre = h @ W_combo (K = 64!) ----
    // pass A: cols 0..63 (w0a | w0b) -> f0
    {
        u64 acc[32];
#pragma unroll
        for (int q = 0; q < 32; q++) acc[q] = 0ull;
#pragma unroll 4
        for (int j = 0; j < 64; j++) {
            const float hj = hloc[j];
            const u64 l2 = pk2(hj, hj);
            const ulonglong2* wr = reinterpret_cast<const ulonglong2*>(sm + SM_WC + j * 160);
#pragma unroll
            for (int q = 0; q < 16; q++) {
                ulonglong2 w = wr[q];
                acc[2 * q]     = fma2(l2, w.x, acc[2 * q]);
                acc[2 * q + 1] = fma2(l2, w.y, acc[2 * q + 1]);
            }
        }
        float accf[64];
#pragma unroll
        for (int q = 0; q < 32; q++) up2(accf[2 * q], accf[2 * q + 1], acc[q]);
#pragma unroll
        for (int u = 0; u < 32; u++)
            buf[lane * 33 + u] = INV2 * (accf[u] * tp0a + accf[32 + u] * tp0b);
        __syncwarp();
#pragma unroll
        for (int rr = 0; rr < 32; rr++)
            feat_out[(size_t)(ebase + rr) * 288 + 0 + lane] = buf[rr * 33 + lane];
        __syncwarp();
    }

    // pass B: cols 64..127 (w1a | w1b) -> f1 (96 cols)
    {
        u64 acc[32];
#pragma unroll
        for (int q = 0; q < 32; q++) acc[q] = 0ull;
#pragma unroll 4
        for (int j = 0; j < 64; j++) {
            const float hj = hloc[j];
            const u64 l2 = pk2(hj, hj);
            const ulonglong2* wr = reinterpret_cast<const ulonglong2*>(sm + SM_WC + j * 160 + 64);
#pragma unroll
            for (int q = 0; q < 16; q++) {
                ulonglong2 w = wr[q];
                acc[2 * q]     = fma2(l2, w.x, acc[2 * q]);
                acc[2 * q + 1] = fma2(l2, w.y, acc[2 * q + 1]);
            }
        }
        float accf[64];
#pragma unroll
        for (int q = 0; q < 32; q++) up2(accf[2 * q], accf[2 * q + 1], acc[q]);
#pragma unroll
        for (int t = 0; t < 3; t++) {
#pragma unroll
            for (int u = 0; u < 32; u++) {
                const int cc = 32 * t + u, m = cc / 3, i = cc % 3;
                buf[lane * 33 + u] = INV2 * (accf[m] * tp1a[i] + accf[32 + m] * tp1b[i]);
            }
            __syncwarp();
#pragma unroll
            for (int rr = 0; rr < 32; rr++)
                feat_out[(size_t)(ebase + rr) * 288 + 32 + 32 * t + lane] =
                    buf[rr * 33 + lane];
            __syncwarp();
        }
    }

    // pass C: cols 128..159 (w2) -> f2 (160 cols)
    {
        u64 acc[16];
#pragma unroll
        for (int q = 0; q < 16; q++) acc[q] = 0ull;
#pragma unroll 4
        for (int j = 0; j < 64; j++) {
            const float hj = hloc[j];
            const u64 l2 = pk2(hj, hj);
            const ulonglong2* wr = reinterpret_cast<const ulonglong2*>(sm + SM_WC + j * 160 + 128);
#pragma unroll
            for (int q = 0; q < 8; q++) {
                ulonglong2 w = wr[q];
                acc[2 * q]     = fma2(l2, w.x, acc[2 * q]);
                acc[2 * q + 1] = fma2(l2, w.y, acc[2 * q + 1]);
            }
        }
        float accf[32];
#pragma unroll
        for (int q = 0; q < 16; q++) up2(accf[2 * q], accf[2 * q + 1], acc[q]);
#pragma unroll
        for (int t = 0; t < 5; t++) {
#pragma unroll
            for (int u = 0; u < 32; u++) {
                const int cc = 32 * t + u, m = cc / 5, i = cc % 5;
                buf[lane * 33 + u] = accf[m] * tp2[i];
            }
            __syncwarp();
#pragma unroll
            for (int rr = 0; rr < 32; rr++)
                feat_out[(size_t)(ebase + rr) * 288 + 128 + 32 * t + lane] =
                    buf[rr * 33 + lane];
            __syncwarp();
        }
    }
}

extern "C" void kernel_launch(void* const* d_in, const int* in_sizes, int n_in,
                              void* d_out, int out_size)
{
    const int*   eidx   = (const int*)  d_in[0];
    const float* esh    = (const float*)d_in[1];
    const float* elen   = (const float*)d_in[2];
    const float* onehot = (const float*)d_in[3];
    const float* bw     = (const float*)d_in[4];
    const float* tpw    = (const float*)d_in[5];
    const float* W0     = (const float*)d_in[6];
    const float* W1     = (const float*)d_in[7];
    const float* We     = (const float*)d_in[8];
    float* out = (float*)d_out;

    const int E = in_sizes[0] / 2;       // edge_index is (2, E)
    const int blocks = E / THREADS;      // E = 524288 -> 1024 blocks

    combo_kernel<<<(64 * 160 + 255) / 256, 256>>>(W1, We);

    cudaFuncSetAttribute(e3_fused_kernel,
                         cudaFuncAttributeMaxDynamicSharedMemorySize, SMEM_BYTES);
    e3_fused_kernel<<<blocks, THREADS, SMEM_BYTES>>>(
        eidx, esh, elen, onehot, bw, tpw, W0, W1, out, E);
}